// round 8
// baseline (speedup 1.0000x reference)
#include <cuda_runtime.h>

// ---------------------------------------------------------------------------
// RNN_32109175505717: 3-layer tanh RNN (B=4096, T=128, HID=64, F=14) + FC head
// R8: R7 skeleton (512 thr, k-split 8, 4j x 8e tile — measured local optimum
// of the smem-crossbar model at ~3970 L1-cyc/phase) + latency trims:
//   - x(t+1) prefetched into registers at step top (LDG off the critical phase)
//   - biases in registers (no per-phase LDS)
//   - L1/L2 matvecs fused into one 16-iter loop over [Wih|Whh]*[h_prev;h_cur]
//     (contiguous smem layouts make this free)
// ---------------------------------------------------------------------------

#define HID        64
#define F_IN       14
#define T_STEPS    128
#define B_TOTAL    4096
#define ELEMS_BLK  32
#define NTHREADS   512
#define NBLOCKS    (B_TOTAL / ELEMS_BLK)   // 128

typedef unsigned long long ull;

// ---- smem layout ----------------------------------------------------------
// float region (weights transposed to [k][64j]); IH before HH so layer L's
// combined 128-row matrix [Wih_L ; Whh_L] is contiguous.
#define WF_HH0   0
#define WF_IH1   (WF_HH0 + 64*64)
#define WF_HH1   (WF_IH1 + 64*64)
#define WF_IH2   (WF_HH1 + 64*64)
#define WF_HH2   (WF_IH2 + 64*64)
#define WF_IH0   (WF_HH2 + 64*64)          // 14*64
#define WF_END   (WF_IH0 + 14*64)          // 21376 floats
// ull region: H0,H1,H2 contiguous so [H_{L-1}new ; H_L old] is one array.
#define U_BASE   (WF_END / 2)
#define U_H0     (U_BASE)                  // [64k][16 ep]
#define U_H1     (U_H0 + 1024)
#define U_H2     (U_H1 + 1024)
#define U_XS     (U_H2 + 1024)             // [14f][16 ep]
#define U_RED    (U_XS + 224)              // [4 q][64 j][16 ep]
#define U_BIAS   (U_RED + 4096)            // 192 f32
#define U_FCRED  (U_BIAS + 96)             // 256 f32
#define SMEM_ULL (U_FCRED + 128)
#define SMEM_BYTES (SMEM_ULL * 8)          // ~146.5 KB

// ---- f32x2 helpers --------------------------------------------------------
__device__ __forceinline__ ull pack2(float lo, float hi) {
    ull r; asm("mov.b64 %0, {%1, %2};" : "=l"(r) : "f"(lo), "f"(hi)); return r;
}
__device__ __forceinline__ void unpack2(ull v, float& lo, float& hi) {
    asm("mov.b64 {%0, %1}, %2;" : "=f"(lo), "=f"(hi) : "l"(v));
}
__device__ __forceinline__ ull fma2(ull a, ull b, ull c) {
    ull d; asm("fma.rn.f32x2 %0, %1, %2, %3;" : "=l"(d) : "l"(a), "l"(b), "l"(c));
    return d;
}
__device__ __forceinline__ ull add2(ull a, ull b) {
    ull d; asm("add.rn.f32x2 %0, %1, %2;" : "=l"(d) : "l"(a), "l"(b));
    return d;
}
__device__ __forceinline__ float fast_tanh(float x) {
    x = fminf(fmaxf(x, -12.0f), 12.0f);
    float e = __expf(x + x);
    return __fdividef(e - 1.0f, e + 1.0f);
}
__device__ __forceinline__ ull tanh2(ull v) {
    float a, b; unpack2(v, a, b);
    return pack2(fast_tanh(a), fast_tanh(b));
}

// ---- matvec partial -------------------------------------------------------
// wf: [k][64j] f32.  hsrc: [k][16 ep] ull.  acc a[4 j][4 ep-ull].
__device__ __forceinline__ void mv_part(const float* __restrict__ wf,
                                        const ull* __restrict__ hsrc,
                                        int koff, int nk, int jq4, int ep0,
                                        ull a[4][4])
{
#pragma unroll 8
    for (int k = 0; k < nk; ++k) {
        const ull* hr = hsrc + (koff + k) * 16 + ep0;
        ulonglong2 h01 = *reinterpret_cast<const ulonglong2*>(hr);
        ulonglong2 h23 = *reinterpret_cast<const ulonglong2*>(hr + 2);
        float4 wv = *reinterpret_cast<const float4*>(wf + (koff + k) * 64 + jq4);
        ull pw0 = pack2(wv.x, wv.x), pw1 = pack2(wv.y, wv.y);
        ull pw2 = pack2(wv.z, wv.z), pw3 = pack2(wv.w, wv.w);
        a[0][0] = fma2(h01.x, pw0, a[0][0]); a[0][1] = fma2(h01.y, pw0, a[0][1]);
        a[0][2] = fma2(h23.x, pw0, a[0][2]); a[0][3] = fma2(h23.y, pw0, a[0][3]);
        a[1][0] = fma2(h01.x, pw1, a[1][0]); a[1][1] = fma2(h01.y, pw1, a[1][1]);
        a[1][2] = fma2(h23.x, pw1, a[1][2]); a[1][3] = fma2(h23.y, pw1, a[1][3]);
        a[2][0] = fma2(h01.x, pw2, a[2][0]); a[2][1] = fma2(h01.y, pw2, a[2][1]);
        a[2][2] = fma2(h23.x, pw2, a[2][2]); a[2][3] = fma2(h23.y, pw2, a[2][3]);
        a[3][0] = fma2(h01.x, pw3, a[3][0]); a[3][1] = fma2(h01.y, pw3, a[3][1]);
        a[3][2] = fma2(h23.x, pw3, a[3][2]); a[3][3] = fma2(h23.y, pw3, a[3][3]);
    }
}

__global__ void __launch_bounds__(NTHREADS, 1)
rnn_fused_kernel(const float* __restrict__ x,
                 const float* __restrict__ Wih0, const float* __restrict__ Whh0,
                 const float* __restrict__ bih0, const float* __restrict__ bhh0,
                 const float* __restrict__ Wih1, const float* __restrict__ Whh1,
                 const float* __restrict__ bih1, const float* __restrict__ bhh1,
                 const float* __restrict__ Wih2, const float* __restrict__ Whh2,
                 const float* __restrict__ bih2, const float* __restrict__ bhh2,
                 const float* __restrict__ fc1w, const float* __restrict__ fc1b,
                 const float* __restrict__ fc2w, const float* __restrict__ fc2b,
                 float* __restrict__ out)
{
    extern __shared__ ull smu[];
    float* smf = (float*)smu;
    const int tid = threadIdx.x;

    // ---- stage weights transposed [k][j] fp32 ----
    {
        const float* gsrc[5] = { Whh0, Wih1, Whh1, Wih2, Whh2 };
        const int    goff[5] = { WF_HH0, WF_IH1, WF_HH1, WF_IH2, WF_HH2 };
#pragma unroll
        for (int m = 0; m < 5; ++m) {
            const float* g = gsrc[m];
            float* s = smf + goff[m];
            for (int idx = tid; idx < 64 * 64; idx += NTHREADS) {
                int j = idx >> 6, k = idx & 63;     // g[j][k]
                s[k * 64 + j] = g[idx];
            }
        }
        for (int idx = tid; idx < 64 * F_IN; idx += NTHREADS) {
            int j = idx / F_IN, f = idx - j * F_IN;
            smf[WF_IH0 + f * 64 + j] = Wih0[idx];
        }
    }
    for (int i = tid; i < 3 * 1024; i += NTHREADS) smu[U_H0 + i] = 0ull;
    float* bias_s = (float*)(smu + U_BIAS);
    if (tid < 64)       bias_s[tid] = bih0[tid] + bhh0[tid];
    else if (tid < 128) bias_s[tid] = bih1[tid - 64] + bhh1[tid - 64];
    else if (tid < 192) bias_s[tid] = bih2[tid - 128] + bhh2[tid - 128];

    // ---- producer mapping ----
    const int w    = tid >> 5;
    const int lane = tid & 31;
    const int kch  = w >> 3;             // 0,1
    const int jqh  = w & 7;              // 0..7
    const int kcl  = lane >> 3;          // 0..3
    const int jql  = (lane >> 2) & 1;
    const int u    = lane & 3;
    const int jq   = jqh * 2 + jql;      // 0..15
    const int jq4  = jq * 4;
    const int ep0  = u * 4;
    const int kc   = kch * 4 + kcl;      // 0..7
    const int k0c  = kc * 16;            // combined-128k start (L1/L2)
    const int k0   = kc * 8;             // 64k split (L0 hh)
    const int f0   = kc * 2;
    const int fn   = (F_IN - f0) >= 2 ? 2 : ((F_IN - f0) > 0 ? (F_IN - f0) : 0);
    const bool do_sts = ((kcl & 1) == 0);        // kcl 0 or 2 store partials
    const int q    = (kcl >> 1) * 2 + kch;       // red quadrant 0..3

    // ---- finisher mapping (all 512 threads) ----
    const int fj  = tid >> 3;            // 0..63 (j)
    const int fep = (tid & 7) * 2;       // ep pair {fep, fep+1}

    const float* xblk = x + (size_t)blockIdx.x * ELEMS_BLK * T_STEPS * F_IN;
    float* xs_f = (float*)(smu + U_XS);
    ull* red = smu + U_RED;
    ull* H[3] = { smu + U_H0, smu + U_H1, smu + U_H2 };

    // x-staging role: thread handles one scalar (e,f) if tid < 448
    const int xe = tid / F_IN;
    const int xf = tid - xe * F_IN;
    const bool xactive = (tid < ELEMS_BLK * F_IN);

    // stage x(t=0)
    if (xactive)
        xs_f[xf * ELEMS_BLK + xe] = xblk[xe * (T_STEPS * F_IN) + xf];
    __syncthreads();

    // biases in registers (bias_s written before the barrier above)
    const float bfj0 = bias_s[fj];
    const float bfj1 = bias_s[64 + fj];
    const float bfj2 = bias_s[128 + fj];

    for (int t = 0; t < T_STEPS; ++t) {
        // ---- prefetch x(t+1) into a register (hidden under layer-0 mv) ----
        float xpre = 0.0f;
        if (xactive && t + 1 < T_STEPS)
            xpre = xblk[xe * (T_STEPS * F_IN) + (t + 1) * F_IN + xf];

        // ================= layer 0 =================
        {
            ull a[4][4] = {};
            if (fn > 0)
                mv_part(smf + WF_IH0, smu + U_XS, f0, fn, jq4, ep0, a);
            mv_part(smf + WF_HH0, H[0], k0, 8, jq4, ep0, a);
#pragma unroll
            for (int jj = 0; jj < 4; ++jj)
#pragma unroll
                for (int pp = 0; pp < 4; ++pp)
                    a[jj][pp] = add2(a[jj][pp],
                                     __shfl_xor_sync(0xffffffffu, a[jj][pp], 8));
            if (do_sts) {
#pragma unroll
                for (int jj = 0; jj < 4; ++jj) {
                    ull* rp = red + ((q * 64) + (jq4 + jj)) * 16 + ep0;
                    *reinterpret_cast<ulonglong2*>(rp) =
                        make_ulonglong2(a[jj][0], a[jj][1]);
                    *reinterpret_cast<ulonglong2*>(rp + 2) =
                        make_ulonglong2(a[jj][2], a[jj][3]);
                }
            }
            __syncthreads();
            // finish + x(t+1) store
            {
                ull s0 = 0ull, s1 = 0ull;
#pragma unroll
                for (int qq = 0; qq < 4; ++qq) {
                    ulonglong2 v = *reinterpret_cast<const ulonglong2*>(
                        red + (qq * 64 + fj) * 16 + fep);
                    s0 = add2(s0, v.x);
                    s1 = add2(s1, v.y);
                }
                ull bp = pack2(bfj0, bfj0);
                ulonglong2 res;
                res.x = tanh2(add2(s0, bp));
                res.y = tanh2(add2(s1, bp));
                *reinterpret_cast<ulonglong2*>(H[0] + fj * 16 + fep) = res;
            }
            if (xactive && t + 1 < T_STEPS)
                xs_f[xf * ELEMS_BLK + xe] = xpre;
            __syncthreads();
        }

        // ================= layer 1: combined [Wih1|Whh1]*[H0new;H1old] =====
        {
            ull a[4][4] = {};
            mv_part(smf + WF_IH1, H[0], k0c, 16, jq4, ep0, a);
#pragma unroll
            for (int jj = 0; jj < 4; ++jj)
#pragma unroll
                for (int pp = 0; pp < 4; ++pp)
                    a[jj][pp] = add2(a[jj][pp],
                                     __shfl_xor_sync(0xffffffffu, a[jj][pp], 8));
            if (do_sts) {
#pragma unroll
                for (int jj = 0; jj < 4; ++jj) {
                    ull* rp = red + ((q * 64) + (jq4 + jj)) * 16 + ep0;
                    *reinterpret_cast<ulonglong2*>(rp) =
                        make_ulonglong2(a[jj][0], a[jj][1]);
                    *reinterpret_cast<ulonglong2*>(rp + 2) =
                        make_ulonglong2(a[jj][2], a[jj][3]);
                }
            }
            __syncthreads();
            {
                ull s0 = 0ull, s1 = 0ull;
#pragma unroll
                for (int qq = 0; qq < 4; ++qq) {
                    ulonglong2 v = *reinterpret_cast<const ulonglong2*>(
                        red + (qq * 64 + fj) * 16 + fep);
                    s0 = add2(s0, v.x);
                    s1 = add2(s1, v.y);
                }
                ull bp = pack2(bfj1, bfj1);
                ulonglong2 res;
                res.x = tanh2(add2(s0, bp));
                res.y = tanh2(add2(s1, bp));
                *reinterpret_cast<ulonglong2*>(H[1] + fj * 16 + fep) = res;
            }
            __syncthreads();
        }

        // ================= layer 2: combined [Wih2|Whh2]*[H1new;H2old] =====
        {
            ull a[4][4] = {};
            mv_part(smf + WF_IH2, H[1], k0c, 16, jq4, ep0, a);
#pragma unroll
            for (int jj = 0; jj < 4; ++jj)
#pragma unroll
                for (int pp = 0; pp < 4; ++pp)
                    a[jj][pp] = add2(a[jj][pp],
                                     __shfl_xor_sync(0xffffffffu, a[jj][pp], 8));
            if (do_sts) {
#pragma unroll
                for (int jj = 0; jj < 4; ++jj) {
                    ull* rp = red + ((q * 64) + (jq4 + jj)) * 16 + ep0;
                    *reinterpret_cast<ulonglong2*>(rp) =
                        make_ulonglong2(a[jj][0], a[jj][1]);
                    *reinterpret_cast<ulonglong2*>(rp + 2) =
                        make_ulonglong2(a[jj][2], a[jj][3]);
                }
            }
            __syncthreads();
            {
                ull s0 = 0ull, s1 = 0ull;
#pragma unroll
                for (int qq = 0; qq < 4; ++qq) {
                    ulonglong2 v = *reinterpret_cast<const ulonglong2*>(
                        red + (qq * 64 + fj) * 16 + fep);
                    s0 = add2(s0, v.x);
                    s1 = add2(s1, v.y);
                }
                ull bp = pack2(bfj2, bfj2);
                ulonglong2 res;
                res.x = tanh2(add2(s0, bp));
                res.y = tanh2(add2(s1, bp));
                *reinterpret_cast<ulonglong2*>(H[2] + fj * 16 + fep) = res;
            }
            __syncthreads();
        }
    }

    // ---- FC head on final h2 ([k][16 ep] ull == [k][32 e] floats) ----
    const float* h2f = (const float*)H[2];
    if (tid < 256) {
        int e  = tid >> 3;
        int mg = tid & 7;
        float contrib = 0.0f;
#pragma unroll
        for (int mi = 0; mi < 4; ++mi) {
            int m = mg * 4 + mi;
            float s = fc1b[m];
#pragma unroll 16
            for (int k = 0; k < HID; ++k)
                s = fmaf(fc1w[m * HID + k], h2f[k * 32 + e], s);
            contrib = fmaf(fc2w[m], fmaxf(s, 0.0f), contrib);
        }
        float* fred = (float*)(smu + U_FCRED);
        fred[tid] = contrib;
    }
    __syncthreads();
    if (tid < ELEMS_BLK) {
        float* fred = (float*)(smu + U_FCRED);
        float s = fc2b[0];
#pragma unroll
        for (int i = 0; i < 8; ++i) s += fred[tid * 8 + i];
        out[blockIdx.x * ELEMS_BLK + tid] = s;
    }
}

extern "C" void kernel_launch(void* const* d_in, const int* in_sizes, int n_in,
                              void* d_out, int out_size)
{
    const float* x    = (const float*)d_in[0];
    const float* Wih0 = (const float*)d_in[1];
    const float* Whh0 = (const float*)d_in[2];
    const float* bih0 = (const float*)d_in[3];
    const float* bhh0 = (const float*)d_in[4];
    const float* Wih1 = (const float*)d_in[5];
    const float* Whh1 = (const float*)d_in[6];
    const float* bih1 = (const float*)d_in[7];
    const float* bhh1 = (const float*)d_in[8];
    const float* Wih2 = (const float*)d_in[9];
    const float* Whh2 = (const float*)d_in[10];
    const float* bih2 = (const float*)d_in[11];
    const float* bhh2 = (const float*)d_in[12];
    const float* fc1w = (const float*)d_in[13];
    const float* fc1b = (const float*)d_in[14];
    const float* fc2w = (const float*)d_in[15];
    const float* fc2b = (const float*)d_in[16];
    float* out = (float*)d_out;

    cudaFuncSetAttribute(rnn_fused_kernel,
                         cudaFuncAttributeMaxDynamicSharedMemorySize, SMEM_BYTES);

    rnn_fused_kernel<<<NBLOCKS, NTHREADS, SMEM_BYTES>>>(
        x, Wih0, Whh0, bih0, bhh0,
        Wih1, Whh1, bih1, bhh1,
        Wih2, Whh2, bih2, bhh2,
        fc1w, fc1b, fc2w, fc2b, out);
}

// round 9
// speedup vs baseline: 1.1254x; 1.1254x over previous
#include <cuda_runtime.h>

// ---------------------------------------------------------------------------
// RNN_32109175505717: 3-layer tanh RNN (B=4096, T=128, HID=64, F=14) + FC head
// R9 = R7 base (512 thr, k-split 8, 4j x 8e, separate mv loops) with:
//   - shfl-free reduction: all kcl lanes store to 8-quadrant red with
//     jql offset +18 ull (144B = 16 mod 128) -> provably conflict-free STS.128
//     (phase banks {0,32,64,96,16,48,80,112})
//   - biases in registers
//   - x(t+1) prefetched into a register at step top (store in L0 finish phase)
// ---------------------------------------------------------------------------

#define HID        64
#define F_IN       14
#define T_STEPS    128
#define B_TOTAL    4096
#define ELEMS_BLK  32
#define NTHREADS   512
#define NBLOCKS    (B_TOTAL / ELEMS_BLK)   // 128

typedef unsigned long long ull;

// ---- smem layout ----------------------------------------------------------
#define WF_HH0   0
#define WF_IH1   (WF_HH0 + 64*64)
#define WF_HH1   (WF_IH1 + 64*64)
#define WF_IH2   (WF_HH1 + 64*64)
#define WF_HH2   (WF_IH2 + 64*64)
#define WF_IH0   (WF_HH2 + 64*64)          // 14*64
#define WF_END   (WF_IH0 + 14*64)          // 21376 floats
#define U_BASE   (WF_END / 2)
#define U_H0     (U_BASE)                  // [64k][16 ep]
#define U_H1     (U_H0 + 1024)
#define U_H2     (U_H1 + 1024)
#define U_XS     (U_H2 + 1024)             // [14f][16 ep]
#define U_RED    (U_XS + 224)              // [8 q][32 jrow][36] = 9216 ull
#define RED_Q    1152                      // 32*36
#define RED_ROW  36
#define U_BIAS   (U_RED + 9216)            // 192 f32
#define U_FCRED  (U_BIAS + 96)             // 256 f32
#define SMEM_ULL (U_FCRED + 128)
#define SMEM_BYTES (SMEM_ULL * 8)          // ~187 KB

// ---- f32x2 helpers --------------------------------------------------------
__device__ __forceinline__ ull pack2(float lo, float hi) {
    ull r; asm("mov.b64 %0, {%1, %2};" : "=l"(r) : "f"(lo), "f"(hi)); return r;
}
__device__ __forceinline__ void unpack2(ull v, float& lo, float& hi) {
    asm("mov.b64 {%0, %1}, %2;" : "=f"(lo), "=f"(hi) : "l"(v));
}
__device__ __forceinline__ ull fma2(ull a, ull b, ull c) {
    ull d; asm("fma.rn.f32x2 %0, %1, %2, %3;" : "=l"(d) : "l"(a), "l"(b), "l"(c));
    return d;
}
__device__ __forceinline__ ull add2(ull a, ull b) {
    ull d; asm("add.rn.f32x2 %0, %1, %2;" : "=l"(d) : "l"(a), "l"(b));
    return d;
}
__device__ __forceinline__ float fast_tanh(float x) {
    x = fminf(fmaxf(x, -12.0f), 12.0f);
    float e = __expf(x + x);
    return __fdividef(e - 1.0f, e + 1.0f);
}
__device__ __forceinline__ ull tanh2(ull v) {
    float a, b; unpack2(v, a, b);
    return pack2(fast_tanh(a), fast_tanh(b));
}

// ---- matvec partial -------------------------------------------------------
__device__ __forceinline__ void mv_part(const float* __restrict__ wf,
                                        const ull* __restrict__ hsrc,
                                        int koff, int nk, int jq4, int ep0,
                                        ull a[4][4])
{
#pragma unroll 8
    for (int k = 0; k < nk; ++k) {
        const ull* hr = hsrc + (koff + k) * 16 + ep0;
        ulonglong2 h01 = *reinterpret_cast<const ulonglong2*>(hr);
        ulonglong2 h23 = *reinterpret_cast<const ulonglong2*>(hr + 2);
        float4 wv = *reinterpret_cast<const float4*>(wf + (koff + k) * 64 + jq4);
        ull pw0 = pack2(wv.x, wv.x), pw1 = pack2(wv.y, wv.y);
        ull pw2 = pack2(wv.z, wv.z), pw3 = pack2(wv.w, wv.w);
        a[0][0] = fma2(h01.x, pw0, a[0][0]); a[0][1] = fma2(h01.y, pw0, a[0][1]);
        a[0][2] = fma2(h23.x, pw0, a[0][2]); a[0][3] = fma2(h23.y, pw0, a[0][3]);
        a[1][0] = fma2(h01.x, pw1, a[1][0]); a[1][1] = fma2(h01.y, pw1, a[1][1]);
        a[1][2] = fma2(h23.x, pw1, a[1][2]); a[1][3] = fma2(h23.y, pw1, a[1][3]);
        a[2][0] = fma2(h01.x, pw2, a[2][0]); a[2][1] = fma2(h01.y, pw2, a[2][1]);
        a[2][2] = fma2(h23.x, pw2, a[2][2]); a[2][3] = fma2(h23.y, pw2, a[2][3]);
        a[3][0] = fma2(h01.x, pw3, a[3][0]); a[3][1] = fma2(h01.y, pw3, a[3][1]);
        a[3][2] = fma2(h23.x, pw3, a[3][2]); a[3][3] = fma2(h23.y, pw3, a[3][3]);
    }
}

__global__ void __launch_bounds__(NTHREADS, 1)
rnn_fused_kernel(const float* __restrict__ x,
                 const float* __restrict__ Wih0, const float* __restrict__ Whh0,
                 const float* __restrict__ bih0, const float* __restrict__ bhh0,
                 const float* __restrict__ Wih1, const float* __restrict__ Whh1,
                 const float* __restrict__ bih1, const float* __restrict__ bhh1,
                 const float* __restrict__ Wih2, const float* __restrict__ Whh2,
                 const float* __restrict__ bih2, const float* __restrict__ bhh2,
                 const float* __restrict__ fc1w, const float* __restrict__ fc1b,
                 const float* __restrict__ fc2w, const float* __restrict__ fc2b,
                 float* __restrict__ out)
{
    extern __shared__ ull smu[];
    float* smf = (float*)smu;
    const int tid = threadIdx.x;

    // ---- stage weights transposed [k][j] fp32 ----
    {
        const float* gsrc[5] = { Whh0, Wih1, Whh1, Wih2, Whh2 };
        const int    goff[5] = { WF_HH0, WF_IH1, WF_HH1, WF_IH2, WF_HH2 };
#pragma unroll
        for (int m = 0; m < 5; ++m) {
            const float* g = gsrc[m];
            float* s = smf + goff[m];
            for (int idx = tid; idx < 64 * 64; idx += NTHREADS) {
                int j = idx >> 6, k = idx & 63;
                s[k * 64 + j] = g[idx];
            }
        }
        for (int idx = tid; idx < 64 * F_IN; idx += NTHREADS) {
            int j = idx / F_IN, f = idx - j * F_IN;
            smf[WF_IH0 + f * 64 + j] = Wih0[idx];
        }
    }
    for (int i = tid; i < 3 * 1024; i += NTHREADS) smu[U_H0 + i] = 0ull;
    float* bias_s = (float*)(smu + U_BIAS);
    if (tid < 64)       bias_s[tid] = bih0[tid] + bhh0[tid];
    else if (tid < 128) bias_s[tid] = bih1[tid - 64] + bhh1[tid - 64];
    else if (tid < 192) bias_s[tid] = bih2[tid - 128] + bhh2[tid - 128];

    // ---- producer mapping (identical to R7) ----
    const int w    = tid >> 5;
    const int lane = tid & 31;
    const int kch  = w >> 3;             // 0,1
    const int jqh  = w & 7;              // 0..7
    const int kcl  = lane >> 3;          // 0..3
    const int jql  = (lane >> 2) & 1;
    const int u    = lane & 3;
    const int jq   = jqh * 2 + jql;      // 0..15
    const int jq4  = jq * 4;
    const int ep0  = u * 4;
    const int kc   = kch * 4 + kcl;      // 0..7
    const int k0   = kc * 8;
    const int f0   = kc * 2;
    const int fn   = (F_IN - f0) >= 2 ? 2 : ((F_IN - f0) > 0 ? (F_IN - f0) : 0);
    // red store base: [q=kc][jqh*4+jj][jql*18 + ep0]
    const int sbase = kc * RED_Q + jqh * 4 * RED_ROW + jql * 18 + ep0;

    // ---- finisher mapping ----
    const int fj  = tid >> 3;            // 0..63
    const int fep = (tid & 7) * 2;
    const int fjqh = fj >> 3, fjql = (fj >> 2) & 1, fjj = fj & 3;
    const int fbase = (fjqh * 4 + fjj) * RED_ROW + fjql * 18 + fep;

    const float* xblk = x + (size_t)blockIdx.x * ELEMS_BLK * T_STEPS * F_IN;
    float* xs_f = (float*)(smu + U_XS);
    ull* red = smu + U_RED;
    ull* H[3] = { smu + U_H0, smu + U_H1, smu + U_H2 };

    const int xe = tid / F_IN;
    const int xf = tid - xe * F_IN;
    const bool xactive = (tid < ELEMS_BLK * F_IN);

    if (xactive)
        xs_f[xf * ELEMS_BLK + xe] = xblk[xe * (T_STEPS * F_IN) + xf];
    __syncthreads();

    const float bfj0 = bias_s[fj];
    const float bfj1 = bias_s[64 + fj];
    const float bfj2 = bias_s[128 + fj];

    for (int t = 0; t < T_STEPS; ++t) {
        float xpre = 0.0f;
        if (xactive && t + 1 < T_STEPS)
            xpre = xblk[xe * (T_STEPS * F_IN) + (t + 1) * F_IN + xf];

#pragma unroll
        for (int L = 0; L < 3; ++L) {
            // ---------- matvec (R7 structure: two separate calls) ----------
            ull a[4][4] = {};
            if (L == 0) {
                if (fn > 0)
                    mv_part(smf + WF_IH0, smu + U_XS, f0, fn, jq4, ep0, a);
                mv_part(smf + WF_HH0, H[0], k0, 8, jq4, ep0, a);
            } else if (L == 1) {
                mv_part(smf + WF_IH1, H[0], k0, 8, jq4, ep0, a);
                mv_part(smf + WF_HH1, H[1], k0, 8, jq4, ep0, a);
            } else {
                mv_part(smf + WF_IH2, H[1], k0, 8, jq4, ep0, a);
                mv_part(smf + WF_HH2, H[2], k0, 8, jq4, ep0, a);
            }

            // ---------- store partials: all lanes, conflict-free ----------
#pragma unroll
            for (int jj = 0; jj < 4; ++jj) {
                ull* rp = red + sbase + jj * RED_ROW;
                *reinterpret_cast<ulonglong2*>(rp) =
                    make_ulonglong2(a[jj][0], a[jj][1]);
                *reinterpret_cast<ulonglong2*>(rp + 2) =
                    make_ulonglong2(a[jj][2], a[jj][3]);
            }
            __syncthreads();

            // ---------- finish: sum 8 quadrants, +bias, tanh, write h -----
            {
                ull s0 = 0ull, s1 = 0ull;
#pragma unroll
                for (int qq = 0; qq < 8; ++qq) {
                    ulonglong2 v = *reinterpret_cast<const ulonglong2*>(
                        red + qq * RED_Q + fbase);
                    s0 = add2(s0, v.x);
                    s1 = add2(s1, v.y);
                }
                float bj = (L == 0) ? bfj0 : (L == 1) ? bfj1 : bfj2;
                ull bp = pack2(bj, bj);
                ulonglong2 res;
                res.x = tanh2(add2(s0, bp));
                res.y = tanh2(add2(s1, bp));
                *reinterpret_cast<ulonglong2*>(H[L] + fj * 16 + fep) = res;
            }
            // stage x(t+1) inside layer-0 finish phase
            if (L == 0 && xactive && t + 1 < T_STEPS)
                xs_f[xf * ELEMS_BLK + xe] = xpre;
            __syncthreads();
        }
    }

    // ---- FC head on final h2 ----
    const float* h2f = (const float*)H[2];
    if (tid < 256) {
        int e  = tid >> 3;
        int mg = tid & 7;
        float contrib = 0.0f;
#pragma unroll
        for (int mi = 0; mi < 4; ++mi) {
            int m = mg * 4 + mi;
            float s = fc1b[m];
#pragma unroll 16
            for (int k = 0; k < HID; ++k)
                s = fmaf(fc1w[m * HID + k], h2f[k * 32 + e], s);
            contrib = fmaf(fc2w[m], fmaxf(s, 0.0f), contrib);
        }
        float* fred = (float*)(smu + U_FCRED);
        fred[tid] = contrib;
    }
    __syncthreads();
    if (tid < ELEMS_BLK) {
        float* fred = (float*)(smu + U_FCRED);
        float s = fc2b[0];
#pragma unroll
        for (int i = 0; i < 8; ++i) s += fred[tid * 8 + i];
        out[blockIdx.x * ELEMS_BLK + tid] = s;
    }
}

extern "C" void kernel_launch(void* const* d_in, const int* in_sizes, int n_in,
                              void* d_out, int out_size)
{
    const float* x    = (const float*)d_in[0];
    const float* Wih0 = (const float*)d_in[1];
    const float* Whh0 = (const float*)d_in[2];
    const float* bih0 = (const float*)d_in[3];
    const float* bhh0 = (const float*)d_in[4];
    const float* Wih1 = (const float*)d_in[5];
    const float* Whh1 = (const float*)d_in[6];
    const float* bih1 = (const float*)d_in[7];
    const float* bhh1 = (const float*)d_in[8];
    const float* Wih2 = (const float*)d_in[9];
    const float* Whh2 = (const float*)d_in[10];
    const float* bih2 = (const float*)d_in[11];
    const float* bhh2 = (const float*)d_in[12];
    const float* fc1w = (const float*)d_in[13];
    const float* fc1b = (const float*)d_in[14];
    const float* fc2w = (const float*)d_in[15];
    const float* fc2b = (const float*)d_in[16];
    float* out = (float*)d_out;

    cudaFuncSetAttribute(rnn_fused_kernel,
                         cudaFuncAttributeMaxDynamicSharedMemorySize, SMEM_BYTES);

    rnn_fused_kernel<<<NBLOCKS, NTHREADS, SMEM_BYTES>>>(
        x, Wih0, Whh0, bih0, bhh0,
        Wih1, Whh1, bih1, bhh1,
        Wih2, Whh2, bih2, bhh2,
        fc1w, fc1b, fc2w, fc2b, out);
}

// round 10
// speedup vs baseline: 1.2952x; 1.1509x over previous
#include <cuda_runtime.h>

// ---------------------------------------------------------------------------
// RNN_32109175505717: 3-layer tanh RNN (B=4096, T=128, HID=64, F=14) + FC head
// R10: 256 threads, thread tile 8j x 8e, ksplit 8 via k-INTERLEAVING
// (thread kc owns k = kc + 8*i). Bank-exact layouts: H rows stride 18 ull,
// weight rows stride 68 f32, red RED_Q=1154/RED_ROW=18 -> every smem access
// phase provably conflict-free. mv traffic ~2/3 of R9 at same reduction cost.
// ---------------------------------------------------------------------------

#define HID        64
#define F_IN       14
#define T_STEPS    128
#define B_TOTAL    4096
#define ELEMS_BLK  32
#define NTHREADS   256
#define NBLOCKS    (B_TOTAL / ELEMS_BLK)   // 128

typedef unsigned long long ull;

// ---- float-region offsets (weights, [k][j] with 68-float rows) ------------
#define WROW     68
#define WF_IH0   0                          // 16 rows (14 used)
#define WF_HH0   (WF_IH0 + 16*WROW)         // 64 rows
#define WF_C1    (WF_HH0 + 64*WROW)         // 128 rows: [Wih1;Whh1]
#define WF_C2    (WF_C1 + 128*WROW)         // 128 rows: [Wih2;Whh2]
#define WF_ENDF  (WF_C2 + 128*WROW)         // 22848 floats (even)
// ---- ull-region offsets ---------------------------------------------------
#define HROW     18
#define HSZ      (64*HROW)                  // 1152
#define U_H0     (WF_ENDF/2)                // 11424
#define U_H1     (U_H0 + HSZ)
#define U_H2     (U_H1 + HSZ)
#define U_XS     (U_H2 + HSZ)               // 14 rows x HROW
#define RED_ROW  18
#define RED_Q    1154                       // 64*18 + 2 pad (odd/2 mod 8)
#define U_RED    (U_XS + 14*HROW)
#define U_BIAS   (U_RED + 8*RED_Q)
#define U_FCRED  (U_BIAS + 96)
#define SMEM_ULL (U_FCRED + 128)
#define SMEM_BYTES (SMEM_ULL * 8)           // ~196.7 KB

// ---- f32x2 helpers --------------------------------------------------------
__device__ __forceinline__ ull pack2(float lo, float hi) {
    ull r; asm("mov.b64 %0, {%1, %2};" : "=l"(r) : "f"(lo), "f"(hi)); return r;
}
__device__ __forceinline__ void unpack2(ull v, float& lo, float& hi) {
    asm("mov.b64 {%0, %1}, %2;" : "=f"(lo), "=f"(hi) : "l"(v));
}
__device__ __forceinline__ ull fma2(ull a, ull b, ull c) {
    ull d; asm("fma.rn.f32x2 %0, %1, %2, %3;" : "=l"(d) : "l"(a), "l"(b), "l"(c));
    return d;
}
__device__ __forceinline__ ull add2(ull a, ull b) {
    ull d; asm("add.rn.f32x2 %0, %1, %2;" : "=l"(d) : "l"(a), "l"(b));
    return d;
}
__device__ __forceinline__ float fast_tanh(float x) {
    x = fminf(fmaxf(x, -12.0f), 12.0f);
    float e = __expf(x + x);
    return __fdividef(e - 1.0f, e + 1.0f);
}
__device__ __forceinline__ ull tanh2(ull v) {
    float a, b; unpack2(v, a, b);
    return pack2(fast_tanh(a), fast_tanh(b));
}

// ---- one k-row accumulate: 8j x 4 ep-ull ---------------------------------
__device__ __forceinline__ void mv_one(const float* __restrict__ wf,
                                       const ull* __restrict__ hb,
                                       int k, int jqh8, int ep0, ull a[8][4])
{
    const ull* hr = hb + k * HROW + ep0;
    ulonglong2 h01 = *reinterpret_cast<const ulonglong2*>(hr);
    ulonglong2 h23 = *reinterpret_cast<const ulonglong2*>(hr + 2);
    const float* wr = wf + k * WROW + jqh8;
    float4 wa = *reinterpret_cast<const float4*>(wr);
    float4 wb = *reinterpret_cast<const float4*>(wr + 4);
    ull pw0 = pack2(wa.x, wa.x), pw1 = pack2(wa.y, wa.y);
    ull pw2 = pack2(wa.z, wa.z), pw3 = pack2(wa.w, wa.w);
    ull pw4 = pack2(wb.x, wb.x), pw5 = pack2(wb.y, wb.y);
    ull pw6 = pack2(wb.z, wb.z), pw7 = pack2(wb.w, wb.w);
    a[0][0]=fma2(h01.x,pw0,a[0][0]); a[0][1]=fma2(h01.y,pw0,a[0][1]);
    a[0][2]=fma2(h23.x,pw0,a[0][2]); a[0][3]=fma2(h23.y,pw0,a[0][3]);
    a[1][0]=fma2(h01.x,pw1,a[1][0]); a[1][1]=fma2(h01.y,pw1,a[1][1]);
    a[1][2]=fma2(h23.x,pw1,a[1][2]); a[1][3]=fma2(h23.y,pw1,a[1][3]);
    a[2][0]=fma2(h01.x,pw2,a[2][0]); a[2][1]=fma2(h01.y,pw2,a[2][1]);
    a[2][2]=fma2(h23.x,pw2,a[2][2]); a[2][3]=fma2(h23.y,pw2,a[2][3]);
    a[3][0]=fma2(h01.x,pw3,a[3][0]); a[3][1]=fma2(h01.y,pw3,a[3][1]);
    a[3][2]=fma2(h23.x,pw3,a[3][2]); a[3][3]=fma2(h23.y,pw3,a[3][3]);
    a[4][0]=fma2(h01.x,pw4,a[4][0]); a[4][1]=fma2(h01.y,pw4,a[4][1]);
    a[4][2]=fma2(h23.x,pw4,a[4][2]); a[4][3]=fma2(h23.y,pw4,a[4][3]);
    a[5][0]=fma2(h01.x,pw5,a[5][0]); a[5][1]=fma2(h01.y,pw5,a[5][1]);
    a[5][2]=fma2(h23.x,pw5,a[5][2]); a[5][3]=fma2(h23.y,pw5,a[5][3]);
    a[6][0]=fma2(h01.x,pw6,a[6][0]); a[6][1]=fma2(h01.y,pw6,a[6][1]);
    a[6][2]=fma2(h23.x,pw6,a[6][2]); a[6][3]=fma2(h23.y,pw6,a[6][3]);
    a[7][0]=fma2(h01.x,pw7,a[7][0]); a[7][1]=fma2(h01.y,pw7,a[7][1]);
    a[7][2]=fma2(h23.x,pw7,a[7][2]); a[7][3]=fma2(h23.y,pw7,a[7][3]);
}

template<int NI>
__device__ __forceinline__ void mv_acc(const float* __restrict__ wf,
                                       const ull* __restrict__ hb,
                                       int kc, int jqh8, int ep0, ull a[8][4])
{
#pragma unroll
    for (int i = 0; i < NI; ++i)
        mv_one(wf, hb, kc + 8 * i, jqh8, ep0, a);
}

__global__ void __launch_bounds__(NTHREADS, 1)
rnn_fused_kernel(const float* __restrict__ x,
                 const float* __restrict__ Wih0, const float* __restrict__ Whh0,
                 const float* __restrict__ bih0, const float* __restrict__ bhh0,
                 const float* __restrict__ Wih1, const float* __restrict__ Whh1,
                 const float* __restrict__ bih1, const float* __restrict__ bhh1,
                 const float* __restrict__ Wih2, const float* __restrict__ Whh2,
                 const float* __restrict__ bih2, const float* __restrict__ bhh2,
                 const float* __restrict__ fc1w, const float* __restrict__ fc1b,
                 const float* __restrict__ fc2w, const float* __restrict__ fc2b,
                 float* __restrict__ out)
{
    extern __shared__ ull smu[];
    float* smf = (float*)smu;
    const int tid = threadIdx.x;

    // ---- stage weights [k][j], 68-float rows ----
    for (int idx = tid; idx < 64 * F_IN; idx += NTHREADS) {
        int j = idx / F_IN, f = idx - j * F_IN;          // Wih0[j][f]
        smf[WF_IH0 + f * WROW + j] = Wih0[idx];
    }
    for (int idx = tid; idx < 64 * 64; idx += NTHREADS) {
        int j = idx >> 6, k = idx & 63;
        smf[WF_HH0 + k * WROW + j]         = Whh0[idx];
        smf[WF_C1  + k * WROW + j]         = Wih1[idx];
        smf[WF_C1  + (64 + k) * WROW + j]  = Whh1[idx];
        smf[WF_C2  + k * WROW + j]         = Wih2[idx];
        smf[WF_C2  + (64 + k) * WROW + j]  = Whh2[idx];
    }
    for (int i = tid; i < 3 * HSZ; i += NTHREADS) smu[U_H0 + i] = 0ull;
    float* bias_s = (float*)(smu + U_BIAS);
    if (tid < 64)       bias_s[tid] = bih0[tid] + bhh0[tid];
    else if (tid < 128) bias_s[tid] = bih1[tid - 64] + bhh1[tid - 64];
    else if (tid < 192) bias_s[tid] = bih2[tid - 128] + bhh2[tid - 128];

    // ---- producer mapping: warp = jqh, lane = (kc<<2)|u ----
    const int jqh8 = (tid >> 5) * 8;     // j base (8 j's)
    const int lane = tid & 31;
    const int kc   = lane >> 2;          // 0..7, owns k = kc + 8i
    const int u    = lane & 3;
    const int ep0  = u * 4;
    const int sbase = kc * RED_Q + jqh8 * RED_ROW + ep0;

    // ---- finisher mapping ----
    const int fj  = tid >> 2;            // 0..63
    const int fu  = tid & 3;
    const int fep = fu * 4;
    const int fbase = fj * RED_ROW + fep;

    const float* xblk = x + (size_t)blockIdx.x * ELEMS_BLK * T_STEPS * F_IN;
    ull* red = smu + U_RED;
    ull* H[3] = { smu + U_H0, smu + U_H1, smu + U_H2 };
    float* xs_f = (float*)(smu + U_XS);  // row f at float offset f*2*HROW

    // x staging: 448 scalars, 2 slots per thread
    const int xe0 = tid / F_IN,         xf0 = tid - xe0 * F_IN;
    const int xi1 = tid + NTHREADS;
    const int xe1 = xi1 / F_IN,         xf1 = xi1 - xe1 * F_IN;
    const bool xa1 = (xi1 < ELEMS_BLK * F_IN);   // tid < 192

    xs_f[xf0 * (2 * HROW) + xe0] = xblk[xe0 * (T_STEPS * F_IN) + xf0];
    if (xa1)
        xs_f[xf1 * (2 * HROW) + xe1] = xblk[xe1 * (T_STEPS * F_IN) + xf1];
    __syncthreads();

    const float bfj0 = bias_s[fj];
    const float bfj1 = bias_s[64 + fj];
    const float bfj2 = bias_s[128 + fj];

    for (int t = 0; t < T_STEPS; ++t) {
        // prefetch x(t+1)
        float xp0 = 0.0f, xp1 = 0.0f;
        if (t + 1 < T_STEPS) {
            xp0 = xblk[xe0 * (T_STEPS * F_IN) + (t + 1) * F_IN + xf0];
            if (xa1)
                xp1 = xblk[xe1 * (T_STEPS * F_IN) + (t + 1) * F_IN + xf1];
        }

#pragma unroll
        for (int L = 0; L < 3; ++L) {
            // ---------- matvec ----------
            ull a[8][4] = {};
            if (L == 0) {
                mv_one(smf + WF_IH0, smu + U_XS, kc, jqh8, ep0, a);
                if (kc < 6)
                    mv_one(smf + WF_IH0, smu + U_XS, kc + 8, jqh8, ep0, a);
                mv_acc<8>(smf + WF_HH0, H[0], kc, jqh8, ep0, a);
            } else if (L == 1) {
                // combined [Wih1;Whh1] x [H0;H1] (k = 0..127 interleaved)
                mv_acc<16>(smf + WF_C1, H[0], kc, jqh8, ep0, a);
            } else {
                mv_acc<16>(smf + WF_C2, H[1], kc, jqh8, ep0, a);
            }

            // ---------- store partials (conflict-free) ----------
#pragma unroll
            for (int jj = 0; jj < 8; ++jj) {
                ull* rp = red + sbase + jj * RED_ROW;
                *reinterpret_cast<ulonglong2*>(rp) =
                    make_ulonglong2(a[jj][0], a[jj][1]);
                *reinterpret_cast<ulonglong2*>(rp + 2) =
                    make_ulonglong2(a[jj][2], a[jj][3]);
            }
            __syncthreads();

            // ---------- finish: sum 8 quadrants, +bias, tanh ----------
            {
                ull s0 = 0ull, s1 = 0ull, s2 = 0ull, s3 = 0ull;
#pragma unroll
                for (int q = 0; q < 8; ++q) {
                    const ull* rp = red + q * RED_Q + fbase;
                    ulonglong2 v0 = *reinterpret_cast<const ulonglong2*>(rp);
                    ulonglong2 v1 = *reinterpret_cast<const ulonglong2*>(rp + 2);
                    s0 = add2(s0, v0.x); s1 = add2(s1, v0.y);
                    s2 = add2(s2, v1.x); s3 = add2(s3, v1.y);
                }
                float bj = (L == 0) ? bfj0 : (L == 1) ? bfj1 : bfj2;
                ull bp = pack2(bj, bj);
                ull* hp = H[L] + fj * HROW + fep;
                *reinterpret_cast<ulonglong2*>(hp) =
                    make_ulonglong2(tanh2(add2(s0, bp)), tanh2(add2(s1, bp)));
                *reinterpret_cast<ulonglong2*>(hp + 2) =
                    make_ulonglong2(tanh2(add2(s2, bp)), tanh2(add2(s3, bp)));
            }
            // stage x(t+1) during L0 finish phase
            if (L == 0 && t + 1 < T_STEPS) {
                xs_f[xf0 * (2 * HROW) + xe0] = xp0;
                if (xa1)
                    xs_f[xf1 * (2 * HROW) + xe1] = xp1;
            }
            __syncthreads();
        }
    }

    // ---- FC head on final h2 (row stride 2*HROW floats) ----
    const float* h2f = (const float*)H[2];
    {
        int e  = tid >> 3;
        int mg = tid & 7;
        float contrib = 0.0f;
#pragma unroll
        for (int mi = 0; mi < 4; ++mi) {
            int m = mg * 4 + mi;
            float s = fc1b[m];
#pragma unroll 16
            for (int k = 0; k < HID; ++k)
                s = fmaf(fc1w[m * HID + k], h2f[k * (2 * HROW) + e], s);
            contrib = fmaf(fc2w[m], fmaxf(s, 0.0f), contrib);
        }
        float* fred = (float*)(smu + U_FCRED);
        fred[tid] = contrib;
    }
    __syncthreads();
    if (tid < ELEMS_BLK) {
        float* fred = (float*)(smu + U_FCRED);
        float s = fc2b[0];
#pragma unroll
        for (int i = 0; i < 8; ++i) s += fred[tid * 8 + i];
        out[blockIdx.x * ELEMS_BLK + tid] = s;
    }
}

extern "C" void kernel_launch(void* const* d_in, const int* in_sizes, int n_in,
                              void* d_out, int out_size)
{
    const float* x    = (const float*)d_in[0];
    const float* Wih0 = (const float*)d_in[1];
    const float* Whh0 = (const float*)d_in[2];
    const float* bih0 = (const float*)d_in[3];
    const float* bhh0 = (const float*)d_in[4];
    const float* Wih1 = (const float*)d_in[5];
    const float* Whh1 = (const float*)d_in[6];
    const float* bih1 = (const float*)d_in[7];
    const float* bhh1 = (const float*)d_in[8];
    const float* Wih2 = (const float*)d_in[9];
    const float* Whh2 = (const float*)d_in[10];
    const float* bih2 = (const float*)d_in[11];
    const float* bhh2 = (const float*)d_in[12];
    const float* fc1w = (const float*)d_in[13];
    const float* fc1b = (const float*)d_in[14];
    const float* fc2w = (const float*)d_in[15];
    const float* fc2b = (const float*)d_in[16];
    float* out = (float*)d_out;

    cudaFuncSetAttribute(rnn_fused_kernel,
                         cudaFuncAttributeMaxDynamicSharedMemorySize, SMEM_BYTES);

    rnn_fused_kernel<<<NBLOCKS, NTHREADS, SMEM_BYTES>>>(
        x, Wih0, Whh0, bih0, bhh0,
        Wih1, Whh1, bih1, bhh1,
        Wih2, Whh2, bih2, bhh2,
        fc1w, fc1b, fc2w, fc2b, out);
}

// round 11
// speedup vs baseline: 1.4650x; 1.1311x over previous
#include <cuda_runtime.h>

// ---------------------------------------------------------------------------
// RNN_32109175505717: 3-layer tanh RNN (B=4096, T=128, HID=64, F=14) + FC head
// R11: layer-skew software pipeline. Super-step s runs three INDEPENDENT jobs
//   A: L0(t=s)   B: L1(t=s-1)   C: L2(t=s-2)
// -> ONE mv+sts phase + ONE finish phase = 2 barriers/step (was 6).
// Tile J=8 j x P=2 ep-ull, ksplit S=4 (k-interleaved), 256 threads.
// Red = 3 jobs x 4 quadrants (conflict-free, stride-18 rows).
// Wih0 fused with Whh0 into one 80-row matrix ([x;pad;H0] operand).
// 130 super-steps; H writes predicated for pipeline fill/drain.
// ---------------------------------------------------------------------------

#define HID      64
#define F_IN     14
#define T_STEPS  128
#define ELEMS    32
#define NTHREADS 256
#define NBLOCKS  128
#define NSUPER   (T_STEPS + 2)

typedef unsigned long long ull;

// ---- float-region (weights [k][j], 68-float rows) -------------------------
#define WROW   68
#define WF_A   0                       // 80 rows: [Wih0(14); zero(2); Whh0(64)]
#define WF_B   (WF_A + 80*WROW)        // 128 rows: [Wih1; Whh1]
#define WF_C   (WF_B + 128*WROW)       // 128 rows: [Wih2; Whh2]
#define WF_END (WF_C + 128*WROW)       // 22848 floats
// ---- ull-region -----------------------------------------------------------
#define HROW   18
#define U_XS   (WF_END/2)              // 11424 ; 16 rows (14 used) -> 288 ull
#define U_H0   (U_XS + 16*HROW)        // [64k][16ep] rows stride 18
#define U_H1   (U_H0 + 64*HROW)
#define U_H2   (U_H1 + 64*HROW)
#define U_RED  (U_H2 + 64*HROW)        // 12 quadrants x 1152 ull
#define RED_Q  1152
#define U_END  (U_RED + 12*RED_Q)      // 28992 ull = 231936 B
#define U_FCRED U_RED                  // FC reduction overlays red (post-loop)
#define SMEM_BYTES (U_END * 8)

// ---- f32x2 helpers --------------------------------------------------------
__device__ __forceinline__ ull pack2(float lo, float hi) {
    ull r; asm("mov.b64 %0, {%1, %2};" : "=l"(r) : "f"(lo), "f"(hi)); return r;
}
__device__ __forceinline__ void unpack2(ull v, float& lo, float& hi) {
    asm("mov.b64 {%0, %1}, %2;" : "=f"(lo), "=f"(hi) : "l"(v));
}
__device__ __forceinline__ ull fma2(ull a, ull b, ull c) {
    ull d; asm("fma.rn.f32x2 %0, %1, %2, %3;" : "=l"(d) : "l"(a), "l"(b), "l"(c));
    return d;
}
__device__ __forceinline__ ull add2(ull a, ull b) {
    ull d; asm("add.rn.f32x2 %0, %1, %2;" : "=l"(d) : "l"(a), "l"(b));
    return d;
}
__device__ __forceinline__ float fast_tanh(float x) {
    x = fminf(fmaxf(x, -12.0f), 12.0f);
    float e = __expf(x + x);
    return __fdividef(e - 1.0f, e + 1.0f);
}
__device__ __forceinline__ ull tanh2(ull v) {
    float a, b; unpack2(v, a, b);
    return pack2(fast_tanh(a), fast_tanh(b));
}

// ---- one k-row: 8j x 2 ep-ull --------------------------------------------
__device__ __forceinline__ void mv_one(const float* __restrict__ wf,
                                       const ull* __restrict__ hb,
                                       int k, int w8, int u2, ull a[8][2])
{
    ulonglong2 h = *reinterpret_cast<const ulonglong2*>(hb + k * HROW + u2);
    const float* wr = wf + k * WROW + w8;
    float4 wa = *reinterpret_cast<const float4*>(wr);
    float4 wb = *reinterpret_cast<const float4*>(wr + 4);
    ull p;
    p = pack2(wa.x, wa.x); a[0][0]=fma2(h.x,p,a[0][0]); a[0][1]=fma2(h.y,p,a[0][1]);
    p = pack2(wa.y, wa.y); a[1][0]=fma2(h.x,p,a[1][0]); a[1][1]=fma2(h.y,p,a[1][1]);
    p = pack2(wa.z, wa.z); a[2][0]=fma2(h.x,p,a[2][0]); a[2][1]=fma2(h.y,p,a[2][1]);
    p = pack2(wa.w, wa.w); a[3][0]=fma2(h.x,p,a[3][0]); a[3][1]=fma2(h.y,p,a[3][1]);
    p = pack2(wb.x, wb.x); a[4][0]=fma2(h.x,p,a[4][0]); a[4][1]=fma2(h.y,p,a[4][1]);
    p = pack2(wb.y, wb.y); a[5][0]=fma2(h.x,p,a[5][0]); a[5][1]=fma2(h.y,p,a[5][1]);
    p = pack2(wb.z, wb.z); a[6][0]=fma2(h.x,p,a[6][0]); a[6][1]=fma2(h.y,p,a[6][1]);
    p = pack2(wb.w, wb.w); a[7][0]=fma2(h.x,p,a[7][0]); a[7][1]=fma2(h.y,p,a[7][1]);
}

__global__ void __launch_bounds__(NTHREADS, 1)
rnn_fused_kernel(const float* __restrict__ x,
                 const float* __restrict__ Wih0, const float* __restrict__ Whh0,
                 const float* __restrict__ bih0, const float* __restrict__ bhh0,
                 const float* __restrict__ Wih1, const float* __restrict__ Whh1,
                 const float* __restrict__ bih1, const float* __restrict__ bhh1,
                 const float* __restrict__ Wih2, const float* __restrict__ Whh2,
                 const float* __restrict__ bih2, const float* __restrict__ bhh2,
                 const float* __restrict__ fc1w, const float* __restrict__ fc1b,
                 const float* __restrict__ fc2w, const float* __restrict__ fc2b,
                 float* __restrict__ out)
{
    extern __shared__ ull smu[];
    float* smf = (float*)smu;
    const int tid = threadIdx.x;

    // ---- zero all smem (pad rows / H / xs must be 0) ----
    {
        uint4* p4 = reinterpret_cast<uint4*>(smu);
        for (int i = tid; i < (int)(U_END / 2); i += NTHREADS)
            p4[i] = make_uint4(0, 0, 0, 0);
    }
    __syncthreads();

    // ---- stage weights [k][j] ----
    for (int idx = tid; idx < 64 * F_IN; idx += NTHREADS) {
        int j = idx / F_IN, f = idx - j * F_IN;
        smf[WF_A + f * WROW + j] = Wih0[idx];
    }
    for (int idx = tid; idx < 64 * 64; idx += NTHREADS) {
        int j = idx >> 6, k = idx & 63;
        smf[WF_A + (16 + k) * WROW + j] = Whh0[idx];
        smf[WF_B + k * WROW + j]        = Wih1[idx];
        smf[WF_B + (64 + k) * WROW + j] = Whh1[idx];
        smf[WF_C + k * WROW + j]        = Wih2[idx];
        smf[WF_C + (64 + k) * WROW + j] = Whh2[idx];
    }

    // ---- mappings ----
    const int w    = tid >> 5;
    const int lane = tid & 31;
    const int kc   = lane >> 3;          // 0..3 (S=4, k = kc + 4i)
    const int u    = lane & 7;           // 0..7
    const int w8   = w * 8;
    const int u2   = u * 2;
    const int fj   = tid >> 2;           // 0..63 (finisher j)
    const int fu   = tid & 3;
    const int fo   = fu * 4;             // 4 ull per job
    const int fbase = fj * HROW + fo;

    // biases in registers
    const float bf0 = bih0[fj] + bhh0[fj];
    const float bf1 = bih1[fj] + bhh1[fj];
    const float bf2 = bih2[fj] + bhh2[fj];

    const float* xblk = x + (size_t)blockIdx.x * ELEMS * T_STEPS * F_IN;
    float* xs_f = (float*)(smu + U_XS);          // row f stride 36 f32
    ull* red = smu + U_RED;
    ull* H0 = smu + U_H0; ull* H1 = smu + U_H1; ull* H2 = smu + U_H2;

    // x staging: two scalars per thread (448 total)
    const int xe0 = tid / F_IN,  xf0 = tid - xe0 * F_IN;
    const int xi1 = tid + NTHREADS;
    const int xe1 = xi1 / F_IN,  xf1 = xi1 - xe1 * F_IN;
    const bool xa1 = (xi1 < ELEMS * F_IN);

    xs_f[xf0 * 36 + xe0] = xblk[xe0 * (T_STEPS * F_IN) + xf0];
    if (xa1) xs_f[xf1 * 36 + xe1] = xblk[xe1 * (T_STEPS * F_IN) + xf1];
    __syncthreads();

    for (int s = 0; s < NSUPER; ++s) {
        // prefetch x(s+1)
        float xp0 = 0.0f, xp1 = 0.0f;
        const bool xstage = (s <= T_STEPS - 2);
        if (xstage) {
            xp0 = xblk[xe0 * (T_STEPS * F_IN) + (s + 1) * F_IN + xf0];
            if (xa1) xp1 = xblk[xe1 * (T_STEPS * F_IN) + (s + 1) * F_IN + xf1];
        }

        // ============ MV phase: 3 independent jobs ============
        {   // job A: L0(t=s) over combined [xs(16 rows); H0] and W_A (80 rows)
            ull a[8][2] = {};
#pragma unroll 5
            for (int i = 0; i < 20; ++i)
                mv_one(smf + WF_A, smu + U_XS, kc + 4 * i, w8, u2, a);
#pragma unroll
            for (int jj = 0; jj < 8; ++jj)
                *reinterpret_cast<ulonglong2*>(
                    red + (0 * 4 + kc) * RED_Q + (w8 + jj) * HROW + u2) =
                    make_ulonglong2(a[jj][0], a[jj][1]);
        }
        {   // job B: L1(t=s-1) over [H0; H1] and W_B (128 rows)
            ull a[8][2] = {};
#pragma unroll 8
            for (int i = 0; i < 32; ++i)
                mv_one(smf + WF_B, H0, kc + 4 * i, w8, u2, a);
#pragma unroll
            for (int jj = 0; jj < 8; ++jj)
                *reinterpret_cast<ulonglong2*>(
                    red + (1 * 4 + kc) * RED_Q + (w8 + jj) * HROW + u2) =
                    make_ulonglong2(a[jj][0], a[jj][1]);
        }
        {   // job C: L2(t=s-2) over [H1; H2] and W_C (128 rows)
            ull a[8][2] = {};
#pragma unroll 8
            for (int i = 0; i < 32; ++i)
                mv_one(smf + WF_C, H1, kc + 4 * i, w8, u2, a);
#pragma unroll
            for (int jj = 0; jj < 8; ++jj)
                *reinterpret_cast<ulonglong2*>(
                    red + (2 * 4 + kc) * RED_Q + (w8 + jj) * HROW + u2) =
                    make_ulonglong2(a[jj][0], a[jj][1]);
        }
        __syncthreads();

        // ============ FINISH phase ============
        // job A -> H0 (valid s <= 127)
        if (s <= T_STEPS - 1) {
            ull s0 = 0, s1 = 0, s2 = 0, s3 = 0;
#pragma unroll
            for (int q = 0; q < 4; ++q) {
                const ull* rp = red + q * RED_Q + fbase;
                ulonglong2 v0 = *reinterpret_cast<const ulonglong2*>(rp);
                ulonglong2 v1 = *reinterpret_cast<const ulonglong2*>(rp + 2);
                s0 = add2(s0, v0.x); s1 = add2(s1, v0.y);
                s2 = add2(s2, v1.x); s3 = add2(s3, v1.y);
            }
            ull bp = pack2(bf0, bf0);
            ull* hp = H0 + fbase;
            *reinterpret_cast<ulonglong2*>(hp) =
                make_ulonglong2(tanh2(add2(s0, bp)), tanh2(add2(s1, bp)));
            *reinterpret_cast<ulonglong2*>(hp + 2) =
                make_ulonglong2(tanh2(add2(s2, bp)), tanh2(add2(s3, bp)));
        }
        // job B -> H1 (valid 1 <= s <= 128)
        if (s >= 1 && s <= T_STEPS) {
            ull s0 = 0, s1 = 0, s2 = 0, s3 = 0;
#pragma unroll
            for (int q = 0; q < 4; ++q) {
                const ull* rp = red + (4 + q) * RED_Q + fbase;
                ulonglong2 v0 = *reinterpret_cast<const ulonglong2*>(rp);
                ulonglong2 v1 = *reinterpret_cast<const ulonglong2*>(rp + 2);
                s0 = add2(s0, v0.x); s1 = add2(s1, v0.y);
                s2 = add2(s2, v1.x); s3 = add2(s3, v1.y);
            }
            ull bp = pack2(bf1, bf1);
            ull* hp = H1 + fbase;
            *reinterpret_cast<ulonglong2*>(hp) =
                make_ulonglong2(tanh2(add2(s0, bp)), tanh2(add2(s1, bp)));
            *reinterpret_cast<ulonglong2*>(hp + 2) =
                make_ulonglong2(tanh2(add2(s2, bp)), tanh2(add2(s3, bp)));
        }
        // job C -> H2 (valid s >= 2)
        if (s >= 2) {
            ull s0 = 0, s1 = 0, s2 = 0, s3 = 0;
#pragma unroll
            for (int q = 0; q < 4; ++q) {
                const ull* rp = red + (8 + q) * RED_Q + fbase;
                ulonglong2 v0 = *reinterpret_cast<const ulonglong2*>(rp);
                ulonglong2 v1 = *reinterpret_cast<const ulonglong2*>(rp + 2);
                s0 = add2(s0, v0.x); s1 = add2(s1, v0.y);
                s2 = add2(s2, v1.x); s3 = add2(s3, v1.y);
            }
            ull bp = pack2(bf2, bf2);
            ull* hp = H2 + fbase;
            *reinterpret_cast<ulonglong2*>(hp) =
                make_ulonglong2(tanh2(add2(s0, bp)), tanh2(add2(s1, bp)));
            *reinterpret_cast<ulonglong2*>(hp + 2) =
                make_ulonglong2(tanh2(add2(s2, bp)), tanh2(add2(s3, bp)));
        }
        // stage x(s+1)
        if (xstage) {
            xs_f[xf0 * 36 + xe0] = xp0;
            if (xa1) xs_f[xf1 * 36 + xe1] = xp1;
        }
        __syncthreads();
    }

    // ---- FC head on final h2 (H2 rows stride 36 f32) ----
    const float* h2f = (const float*)H2;
    {
        int e  = tid >> 3;
        int mg = tid & 7;
        float contrib = 0.0f;
#pragma unroll
        for (int mi = 0; mi < 4; ++mi) {
            int m = mg * 4 + mi;
            float sfc = fc1b[m];
#pragma unroll 16
            for (int k = 0; k < HID; ++k)
                sfc = fmaf(fc1w[m * HID + k], h2f[k * 36 + e], sfc);
            contrib = fmaf(fc2w[m], fmaxf(sfc, 0.0f), contrib);
        }
        __syncthreads();                    // red region reads done; reuse it
        float* fred = (float*)(smu + U_FCRED);
        fred[tid] = contrib;
    }
    __syncthreads();
    if (tid < ELEMS) {
        float* fred = (float*)(smu + U_FCRED);
        float sfc = fc2b[0];
#pragma unroll
        for (int i = 0; i < 8; ++i) sfc += fred[tid * 8 + i];
        out[blockIdx.x * ELEMS + tid] = sfc;
    }
}

extern "C" void kernel_launch(void* const* d_in, const int* in_sizes, int n_in,
                              void* d_out, int out_size)
{
    const float* x    = (const float*)d_in[0];
    const float* Wih0 = (const float*)d_in[1];
    const float* Whh0 = (const float*)d_in[2];
    const float* bih0 = (const float*)d_in[3];
    const float* bhh0 = (const float*)d_in[4];
    const float* Wih1 = (const float*)d_in[5];
    const float* Whh1 = (const float*)d_in[6];
    const float* bih1 = (const float*)d_in[7];
    const float* bhh1 = (const float*)d_in[8];
    const float* Wih2 = (const float*)d_in[9];
    const float* Whh2 = (const float*)d_in[10];
    const float* bih2 = (const float*)d_in[11];
    const float* bhh2 = (const float*)d_in[12];
    const float* fc1w = (const float*)d_in[13];
    const float* fc1b = (const float*)d_in[14];
    const float* fc2w = (const float*)d_in[15];
    const float* fc2b = (const float*)d_in[16];
    float* out = (float*)d_out;

    cudaFuncSetAttribute(rnn_fused_kernel,
                         cudaFuncAttributeMaxDynamicSharedMemorySize, SMEM_BYTES);

    rnn_fused_kernel<<<NBLOCKS, NTHREADS, SMEM_BYTES>>>(
        x, Wih0, Whh0, bih0, bhh0,
        Wih1, Whh1, bih1, bhh1,
        Wih2, Whh2, bih2, bhh2,
        fc1w, fc1b, fc2w, fc2b, out);
}